// round 1
// baseline (speedup 1.0000x reference)
#include <cuda_runtime.h>

#define T_TOK 16384
#define HDIM  2048
#define HHALF 1024
#define HQ    512

// ---------------- static device scratch (no allocations allowed) ----------------
__device__ float g_combined[(size_t)T_TOK * HDIM];   // selector input
__device__ float g_hmid[(size_t)T_TOK * HQ];         // selector hidden
__device__ float g_midA[(size_t)T_TOK * HHALF];      // expert intermediates (reused)
__device__ float g_midB[(size_t)T_TOK * HHALF];
__device__ int   g_sel[T_TOK];
__device__ int   g_idx1[T_TOK];
__device__ int   g_idx2[T_TOK];
__device__ int   g_cnt[2];

// ---------------- elementwise: build 'combined' ----------------
__global__ void combined_kernel(const float* __restrict__ x,
                                const float* __restrict__ freq,
                                const float* __restrict__ imp) {
    int i4 = blockIdx.x * blockDim.x + threadIdx.x;
    int e  = i4 * 4;
    if (e >= T_TOK * HDIM) return;
    int t = e / HDIM;
    int h = e % HDIM;
    float s = (h < HHALF) ? freq[t] : imp[t];
    float4 v = *(const float4*)(x + e);
    v.x *= s; v.y *= s; v.z *= s; v.w *= s;
    *(float4*)(g_combined + e) = v;
}

__global__ void init_counters_kernel() {
    g_cnt[0] = 0;
    g_cnt[1] = 0;
}

// ---------------- generic fp32 GEMM: C[r] = A[gather(r)] @ W + bias ----------------
// Tile 128x128, BK=8, 256 threads, 8x8 per thread (4x4 quads at +0/+64 offsets).
// gather: optional A-row indirection. scatter: optional C-row indirection.
// cnt: optional device row count (early-exit tiles). relu: fused activation.
__global__ __launch_bounds__(256, 2)
void gemm_f32(const float* __restrict__ A, const float* __restrict__ W,
              const float* __restrict__ bias, float* __restrict__ C,
              int K, int N, int ldC,
              const int* __restrict__ gather, const int* __restrict__ scatter,
              const int* __restrict__ cnt, int Mfix, int relu) {
    int count = cnt ? *cnt : Mfix;
    int m0 = blockIdx.y * 128;
    if (m0 >= count) return;
    int n0 = blockIdx.x * 128;

    __shared__ float As[8][132];
    __shared__ float Bs[8][132];

    int tid = threadIdx.x;

    // A-load mapping: thread -> (row m, k-quad)
    int am = tid >> 1;            // 0..127
    int ak = (tid & 1) * 4;       // 0 or 4
    int arow = m0 + am;
    const float* aptr = nullptr;
    if (arow < count) {
        int gr = gather ? gather[arow] : arow;
        aptr = A + (size_t)gr * K + ak;
    }
    // B-load mapping: thread -> (k row, n-quad)
    int bk = tid >> 5;            // 0..7
    int bn = (tid & 31) * 4;      // 0..124
    const float* bptr = W + (size_t)bk * N + n0 + bn;

    int tx = tid & 15;            // 0..15 -> n
    int ty = tid >> 4;            // 0..15 -> m

    float acc[8][8];
#pragma unroll
    for (int i = 0; i < 8; i++)
#pragma unroll
        for (int j = 0; j < 8; j++) acc[i][j] = 0.f;

    for (int kk = 0; kk < K; kk += 8) {
        float4 av = make_float4(0.f, 0.f, 0.f, 0.f);
        if (aptr) av = *(const float4*)(aptr + kk);
        float4 bv = *(const float4*)(bptr + (size_t)kk * N);

        __syncthreads();
        As[ak + 0][am] = av.x;
        As[ak + 1][am] = av.y;
        As[ak + 2][am] = av.z;
        As[ak + 3][am] = av.w;
        *(float4*)&Bs[bk][bn] = bv;
        __syncthreads();

#pragma unroll
        for (int k = 0; k < 8; k++) {
            float4 a0 = *(float4*)&As[k][ty * 4];
            float4 a1 = *(float4*)&As[k][64 + ty * 4];
            float4 b0 = *(float4*)&Bs[k][tx * 4];
            float4 b1 = *(float4*)&Bs[k][64 + tx * 4];
            float ar[8] = {a0.x, a0.y, a0.z, a0.w, a1.x, a1.y, a1.z, a1.w};
            float br[8] = {b0.x, b0.y, b0.z, b0.w, b1.x, b1.y, b1.z, b1.w};
#pragma unroll
            for (int i = 0; i < 8; i++)
#pragma unroll
                for (int j = 0; j < 8; j++) acc[i][j] += ar[i] * br[j];
        }
    }

    // epilogue: bias (+relu), scatter store
    int c0 = tx * 4, c1 = 64 + tx * 4;
    const float* bb = bias + n0;
    float bvals[8];
#pragma unroll
    for (int j = 0; j < 4; j++) { bvals[j] = bb[c0 + j]; bvals[4 + j] = bb[c1 + j]; }

#pragma unroll
    for (int i = 0; i < 8; i++) {
        int m = (i < 4) ? (ty * 4 + i) : (64 + ty * 4 + (i - 4));
        int r = m0 + m;
        if (r >= count) continue;
        int orow = scatter ? scatter[r] : r;
        float* cp = C + (size_t)orow * ldC + n0;
        float4 o0, o1;
        o0.x = acc[i][0] + bvals[0]; o0.y = acc[i][1] + bvals[1];
        o0.z = acc[i][2] + bvals[2]; o0.w = acc[i][3] + bvals[3];
        o1.x = acc[i][4] + bvals[4]; o1.y = acc[i][5] + bvals[5];
        o1.z = acc[i][6] + bvals[6]; o1.w = acc[i][7] + bvals[7];
        if (relu) {
            o0.x = fmaxf(o0.x, 0.f); o0.y = fmaxf(o0.y, 0.f);
            o0.z = fmaxf(o0.z, 0.f); o0.w = fmaxf(o0.w, 0.f);
            o1.x = fmaxf(o1.x, 0.f); o1.y = fmaxf(o1.y, 0.f);
            o1.z = fmaxf(o1.z, 0.f); o1.w = fmaxf(o1.w, 0.f);
        }
        *(float4*)(cp + c0) = o0;
        *(float4*)(cp + c1) = o1;
    }
}

// ---------------- selector tail: logits (K=512, N=3) + argmax + compaction ----------------
__global__ void logits_kernel(const float* __restrict__ W2, const float* __restrict__ b2) {
    int warp = (blockIdx.x * blockDim.x + threadIdx.x) >> 5;
    int lane = threadIdx.x & 31;
    if (warp >= T_TOK) return;
    const float* hrow = g_hmid + (size_t)warp * HQ;
    float s0 = 0.f, s1 = 0.f, s2 = 0.f;
    for (int k = lane * 4; k < HQ; k += 128) {
        float4 h = *(const float4*)(hrow + k);
        const float* w = W2 + k * 3;
        s0 += h.x * w[0] + h.y * w[3] + h.z * w[6] + h.w * w[9];
        s1 += h.x * w[1] + h.y * w[4] + h.z * w[7] + h.w * w[10];
        s2 += h.x * w[2] + h.y * w[5] + h.z * w[8] + h.w * w[11];
    }
#pragma unroll
    for (int o = 16; o > 0; o >>= 1) {
        s0 += __shfl_xor_sync(0xffffffffu, s0, o);
        s1 += __shfl_xor_sync(0xffffffffu, s1, o);
        s2 += __shfl_xor_sync(0xffffffffu, s2, o);
    }
    if (lane == 0) {
        s0 += b2[0]; s1 += b2[1]; s2 += b2[2];
        int sel = 0; float best = s0;               // first-occurrence max (jnp.argmax)
        if (s1 > best) { best = s1; sel = 1; }
        if (s2 > best) { sel = 2; }
        g_sel[warp] = sel;
        if (sel == 1)      { int p = atomicAdd(&g_cnt[0], 1); g_idx1[p] = warp; }
        else if (sel == 2) { int p = atomicAdd(&g_cnt[1], 1); g_idx2[p] = warp; }
    }
}

// ---------------- identity path for sel==0 tokens ----------------
__global__ void copy0_kernel(const float* __restrict__ x, float* __restrict__ out) {
    int t = blockIdx.x;
    if (g_sel[t] != 0) return;
    const float4* src = (const float4*)(x + (size_t)t * HDIM);
    float4* dst = (float4*)(out + (size_t)t * HDIM);
    for (int i = threadIdx.x; i < HDIM / 4; i += blockDim.x) dst[i] = src[i];
}

// ---------------- launch ----------------
extern "C" void kernel_launch(void* const* d_in, const int* in_sizes, int n_in,
                              void* d_out, int out_size) {
    const float* x      = (const float*)d_in[0];
    const float* freq   = (const float*)d_in[1];
    const float* imp    = (const float*)d_in[2];
    const float* sel_W1 = (const float*)d_in[3];
    const float* sel_b1 = (const float*)d_in[4];
    const float* sel_W2 = (const float*)d_in[5];
    const float* sel_b2 = (const float*)d_in[6];
    const float* c1_W   = (const float*)d_in[7];
    const float* c1_b   = (const float*)d_in[8];
    const float* f1_W   = (const float*)d_in[9];
    const float* f1_b   = (const float*)d_in[10];
    const float* d1_W   = (const float*)d_in[11];
    const float* d1_b   = (const float*)d_in[12];
    const float* c2_W   = (const float*)d_in[13];
    const float* c2_b   = (const float*)d_in[14];
    const float* f2_W   = (const float*)d_in[15];
    const float* f2_b   = (const float*)d_in[16];
    const float* d2_W   = (const float*)d_in[17];
    const float* d2_b   = (const float*)d_in[18];
    float* out = (float*)d_out;

    float *combined, *hmid, *midA, *midB;
    int *idx1, *idx2, *cnt;
    cudaGetSymbolAddress((void**)&combined, g_combined);
    cudaGetSymbolAddress((void**)&hmid, g_hmid);
    cudaGetSymbolAddress((void**)&midA, g_midA);
    cudaGetSymbolAddress((void**)&midB, g_midB);
    cudaGetSymbolAddress((void**)&idx1, g_idx1);
    cudaGetSymbolAddress((void**)&idx2, g_idx2);
    cudaGetSymbolAddress((void**)&cnt, g_cnt);
    int* cnt1p = cnt + 0;
    int* cnt2p = cnt + 1;

    const int MT = T_TOK / 128;   // 128 M-tiles (worst case)

    // 1) selector input
    combined_kernel<<<(T_TOK * HDIM / 4 + 255) / 256, 256>>>(x, freq, imp);

    // 2) selector hidden: hmid = relu(combined @ sel_W1 + b1)   [16384,2048]x[2048,512]
    gemm_f32<<<dim3(HQ / 128, MT), 256>>>(combined, sel_W1, sel_b1, hmid,
                                          HDIM, HQ, HQ, nullptr, nullptr, nullptr, T_TOK, 1);

    // 3) logits + argmax + per-expert compaction
    init_counters_kernel<<<1, 1>>>();
    logits_kernel<<<T_TOK / 8, 256>>>(sel_W2, sel_b2);

    // 4) identity tokens
    copy0_kernel<<<T_TOK, 128>>>(x, out);

    // 5) expert 1 over compacted rows (gather A, scatter final into out)
    gemm_f32<<<dim3(HHALF / 128, MT), 256>>>(x,    c1_W, c1_b, midA, HDIM,  HHALF, HHALF, idx1, nullptr, cnt1p, T_TOK, 0);
    gemm_f32<<<dim3(HHALF / 128, MT), 256>>>(midA, f1_W, f1_b, midB, HHALF, HHALF, HHALF, nullptr, nullptr, cnt1p, T_TOK, 0);
    gemm_f32<<<dim3(HDIM / 128, MT), 256>>>(midB, d1_W, d1_b, out,  HHALF, HDIM,  HDIM,  nullptr, idx1,    cnt1p, T_TOK, 0);

    // 6) expert 2 over compacted rows (reuses midA/midB with ld=512)
    gemm_f32<<<dim3(HQ / 128, MT), 256>>>(x,    c2_W, c2_b, midA, HDIM, HQ,   HQ,   idx2, nullptr, cnt2p, T_TOK, 0);
    gemm_f32<<<dim3(HQ / 128, MT), 256>>>(midA, f2_W, f2_b, midB, HQ,   HQ,   HQ,   nullptr, nullptr, cnt2p, T_TOK, 0);
    gemm_f32<<<dim3(HDIM / 128, MT), 256>>>(midB, d2_W, d2_b, out,  HQ,   HDIM, HDIM, nullptr, idx2,    cnt2p, T_TOK, 0);
}

// round 8
// speedup vs baseline: 1.2948x; 1.2948x over previous
#include <cuda_runtime.h>
#include <cuda_bf16.h>
#include <cstdint>

#define T_TOK 16384
#define HDIM  2048
typedef __nv_bfloat16 bf16;

// ---------------- static device scratch ----------------
__device__ bf16  g_xhi[(size_t)T_TOK * HDIM];
__device__ bf16  g_xlo[(size_t)T_TOK * HDIM];
__device__ float g_combined[(size_t)T_TOK * HDIM];
__device__ bf16  g_chi[(size_t)T_TOK * HDIM];
__device__ bf16  g_clo[(size_t)T_TOK * HDIM];
__device__ float g_hmid[(size_t)T_TOK * 512];
__device__ bf16  g_mAhi[(size_t)T_TOK * 1024];
__device__ bf16  g_mAlo[(size_t)T_TOK * 1024];
__device__ bf16  g_mBhi[(size_t)T_TOK * 1024];
__device__ bf16  g_mBlo[(size_t)T_TOK * 1024];
// transposed+split weights pool [N][K] layout
#define O_SELW1 0u
#define O_C1 1048576u
#define O_F1 3145728u
#define O_D1 4194304u
#define O_C2 6291456u
#define O_F2 7340032u
#define O_D2 7602176u
#define W_POOL 8650752u
__device__ bf16 g_whi[W_POOL];
__device__ bf16 g_wlo[W_POOL];
__device__ int g_sel[T_TOK];
__device__ int g_idx1[T_TOK];
__device__ int g_idx2[T_TOK];
__device__ int g_fix[T_TOK];
__device__ int g_cnt[4];   // [0]=cnt1 [1]=cnt2 [2]=nfix

// ---------------- helpers ----------------
__device__ __forceinline__ uint32_t smem_u32(const void* p) {
    uint32_t a;
    asm("{ .reg .u64 t; cvta.to.shared.u64 t, %1; cvt.u32.u64 %0, t; }" : "=r"(a) : "l"(p));
    return a;
}
__device__ __forceinline__ void cp16(uint32_t dst, const void* src) {
    asm volatile("cp.async.cg.shared.global [%0], [%1], 16;" :: "r"(dst), "l"(src));
}
#define CP_COMMIT() asm volatile("cp.async.commit_group;" ::: "memory")
#define CP_WAIT1()  asm volatile("cp.async.wait_group 1;" ::: "memory")
#define CP_WAIT0()  asm volatile("cp.async.wait_group 0;" ::: "memory")

__device__ __forceinline__ void ldmx4(uint32_t* r, uint32_t addr) {
    asm volatile("ldmatrix.sync.aligned.m8n8.x4.shared.b16 {%0,%1,%2,%3}, [%4];"
        : "=r"(r[0]), "=r"(r[1]), "=r"(r[2]), "=r"(r[3]) : "r"(addr));
}
__device__ __forceinline__ void mma_bf16(float* c, const uint32_t* a, uint32_t b0, uint32_t b1) {
    asm volatile("mma.sync.aligned.m16n8k16.row.col.f32.bf16.bf16.f32 "
        "{%0,%1,%2,%3}, {%4,%5,%6,%7}, {%8,%9}, {%0,%1,%2,%3};"
        : "+f"(c[0]), "+f"(c[1]), "+f"(c[2]), "+f"(c[3])
        : "r"(a[0]), "r"(a[1]), "r"(a[2]), "r"(a[3]), "r"(b0), "r"(b1));
}
__device__ __forceinline__ void split2(float v, bf16& h, bf16& l) {
    h = __float2bfloat16_rn(v);
    l = __float2bfloat16_rn(v - __bfloat162float(h));
}

// ---------------- prep: split x, build combined + split ----------------
__global__ void prep_kernel(const float* __restrict__ x, const float* __restrict__ freq,
                            const float* __restrict__ imp) {
    size_t i4 = (size_t)blockIdx.x * blockDim.x + threadIdx.x;
    size_t e = i4 * 4;
    if (e >= (size_t)T_TOK * HDIM) return;
    int t = (int)(e / HDIM);
    int h = (int)(e % HDIM);
    float s = (h < 1024) ? freq[t] : imp[t];
    float4 v = *(const float4*)(x + e);
    float c0 = v.x * s, c1 = v.y * s, c2 = v.z * s, c3 = v.w * s;
    bf16 xh[4], xl[4], ch[4], cl[4];
    split2(v.x, xh[0], xl[0]); split2(v.y, xh[1], xl[1]);
    split2(v.z, xh[2], xl[2]); split2(v.w, xh[3], xl[3]);
    split2(c0, ch[0], cl[0]); split2(c1, ch[1], cl[1]);
    split2(c2, ch[2], cl[2]); split2(c3, ch[3], cl[3]);
    *(uint2*)(g_xhi + e) = *(uint2*)xh;
    *(uint2*)(g_xlo + e) = *(uint2*)xl;
    *(uint2*)(g_chi + e) = *(uint2*)ch;
    *(uint2*)(g_clo + e) = *(uint2*)cl;
    float4 cv; cv.x = c0; cv.y = c1; cv.z = c2; cv.w = c3;
    *(float4*)(g_combined + e) = cv;
}

// ---------------- weight transpose + split: W[K][N] -> Wt[N][K] hi/lo ----------------
__global__ void transpose_split_kernel(const float* __restrict__ W, int K, int N,
                                       bf16* __restrict__ hi, bf16* __restrict__ lo) {
    __shared__ float tile[32][33];
    int nb = blockIdx.x * 32, kb = blockIdx.y * 32;
#pragma unroll
    for (int r = 0; r < 4; r++) {
        int k = kb + threadIdx.y + r * 8;
        tile[threadIdx.y + r * 8][threadIdx.x] = W[(size_t)k * N + nb + threadIdx.x];
    }
    __syncthreads();
#pragma unroll
    for (int r = 0; r < 4; r++) {
        int n = nb + threadIdx.y + r * 8;
        int k = kb + threadIdx.x;
        float v = tile[threadIdx.x][threadIdx.y + r * 8];
        bf16 h, l; split2(v, h, l);
        hi[(size_t)n * K + k] = h;
        lo[(size_t)n * K + k] = l;
    }
}

__global__ void init_counters_kernel() { g_cnt[0] = 0; g_cnt[1] = 0; g_cnt[2] = 0; }

// ---------------- mma.sync split-bf16 GEMM ----------------
// C[128,128 tile] = (Ahi+Alo)[gather] @ (Bhi+Blo)^T + bias  (3-term split)
// 8 warps, each 64x32. BK=64 (128B rows, SW128 swizzle). cp.async double buffer.
#define STAGE_BYTES 65536
#define OFF_AH 0
#define OFF_AL 16384
#define OFF_BH 32768
#define OFF_BL 49152
#define GEMM_SMEM (2 * STAGE_BYTES)

__global__ __launch_bounds__(256, 1)
void gemm_mma(const bf16* __restrict__ Ahi, const bf16* __restrict__ Alo, int ldA,
              const bf16* __restrict__ Bhi, const bf16* __restrict__ Blo, int ldB,
              const float* __restrict__ bias, int Kfull,
              float* __restrict__ Cf, int ldCf,
              bf16* __restrict__ Chi, bf16* __restrict__ Clo, int ldCb,
              const int* __restrict__ gather, const int* __restrict__ scatter,
              const int* __restrict__ cnt, int Mfix, int relu) {
    extern __shared__ char sm[];
    int count = cnt ? *cnt : Mfix;
    int m0 = blockIdx.y * 128;
    if (m0 >= count) return;
    int n0 = blockIdx.x * 128;
    uint32_t smb = smem_u32(sm);
    int tid = threadIdx.x, wid = tid >> 5, lane = tid & 31;

    // ---- gmem->smem mapping: row = tid>>1 (0..127), half = tid&1 (two 64B halves)
    int row = tid >> 1, half = tid & 1;
    uint32_t swoff[4];
#pragma unroll
    for (int i = 0; i < 4; i++) {
        uint32_t bo = (uint32_t)row * 128 + half * 64 + i * 16;
        swoff[i] = bo ^ ((bo >> 3) & 0x70);
    }
    int ar = m0 + row; if (ar > count - 1) ar = count - 1;
    int ag = gather ? gather[ar] : ar;
    const bf16* pah = Ahi + (size_t)ag * ldA + half * 32;
    const bf16* pal = Alo + (size_t)ag * ldA + half * 32;
    const bf16* pbh = Bhi + (size_t)(n0 + row) * ldB + half * 32;
    const bf16* pbl = Blo + (size_t)(n0 + row) * ldB + half * 32;

    int nch = Kfull >> 6;

    // ---- compute mapping
    int wr = wid >> 2, wc = wid & 3;
    int m_base = wr * 64, n_base = wc * 32;

    float acc[4][4][4];
#pragma unroll
    for (int a = 0; a < 4; a++)
#pragma unroll
        for (int b = 0; b < 4; b++)
#pragma unroll
            for (int c = 0; c < 4; c++) acc[a][b][c] = 0.f;

    // prologue
    {
        uint32_t st = smb;
#pragma unroll
        for (int i = 0; i < 4; i++) {
            cp16(st + OFF_AH + swoff[i], pah + i * 8);
            cp16(st + OFF_AL + swoff[i], pal + i * 8);
            cp16(st + OFF_BH + swoff[i], pbh + i * 8);
            cp16(st + OFF_BL + swoff[i], pbl + i * 8);
        }
    }
    CP_COMMIT();

    for (int c = 0; c < nch; c++) {
        if (c + 1 < nch) {
            uint32_t st = smb + ((c + 1) & 1) * STAGE_BYTES;
            int ke = (c + 1) * 64;
#pragma unroll
            for (int i = 0; i < 4; i++) {
                cp16(st + OFF_AH + swoff[i], pah + ke + i * 8);
                cp16(st + OFF_AL + swoff[i], pal + ke + i * 8);
                cp16(st + OFF_BH + swoff[i], pbh + ke + i * 8);
                cp16(st + OFF_BL + swoff[i], pbl + ke + i * 8);
            }
            CP_COMMIT();
            CP_WAIT1();
        } else {
            CP_WAIT0();
        }
        __syncthreads();

        uint32_t sb = smb + (c & 1) * STAGE_BYTES;
#pragma unroll
        for (int kk = 0; kk < 4; kk++) {
            // B fragments: 4 n8-tiles via 2x ldmatrix.x4 (hi and lo)
            uint32_t brow = n_base + ((lane & 7) | ((lane >> 1) & 8));
            uint32_t bkb = kk * 32 + ((lane >> 3) & 1) * 16;
            uint32_t bh[8], bl[8];
#pragma unroll
            for (int np = 0; np < 2; np++) {
                uint32_t bo = (brow + np * 16) * 128 + bkb;
                uint32_t ad = sb + (bo ^ ((bo >> 3) & 0x70));
                ldmx4(bh + np * 4, ad + OFF_BH);
                ldmx4(bl + np * 4, ad + OFF_BL);
            }
            uint32_t arow = m_base + (lane & 15);
            uint32_t akb = kk * 32 + ((lane >> 4) & 1) * 16;
#pragma unroll
            for (int mt = 0; mt < 4; mt++) {
                uint32_t bo = (arow + mt * 16) * 128 + akb;
                uint32_t ad = sb + (bo ^ ((bo >> 3) & 0x70));
                uint32_t ah[4], al[4];
                ldmx4(ah, ad + OFF_AH);
                ldmx4(al, ad + OFF_AL);
#pragma unroll
                for (int nt = 0; nt < 4; nt++) {
                    int bi = (nt >> 1) * 4 + (nt & 1) * 2;
                    mma_bf16(acc[mt][nt], ah, bh[bi], bh[bi + 1]);
                    mma_bf16(acc[mt][nt], ah, bl[bi], bl[bi + 1]);
                    mma_bf16(acc[mt][nt], al, bh[bi], bh[bi + 1]);
                }
            }
        }
        __syncthreads();
    }

    // ---- epilogue: bias (+relu), direct stores
#pragma unroll
    for (int mt = 0; mt < 4; mt++) {
#pragma unroll
        for (int h2 = 0; h2 < 2; h2++) {
            int r = m0 + m_base + mt * 16 + h2 * 8 + (lane >> 2);
            if (r >= count) continue;
            int orow = scatter ? scatter[r] : r;
#pragma unroll
            for (int nt = 0; nt < 4; nt++) {
                int col = n0 + n_base + nt * 8 + (lane & 3) * 2;
                float v0 = acc[mt][nt][h2 * 2 + 0] + bias[col];
                float v1 = acc[mt][nt][h2 * 2 + 1] + bias[col + 1];
                if (relu) { v0 = fmaxf(v0, 0.f); v1 = fmaxf(v1, 0.f); }
                if (Cf) {
                    float2 o; o.x = v0; o.y = v1;
                    *(float2*)(Cf + (size_t)orow * ldCf + col) = o;
                }
                if (Chi) {
                    bf16 h0, l0, h1, l1;
                    split2(v0, h0, l0); split2(v1, h1, l1);
                    size_t co = (size_t)r * ldCb + col;
                    __nv_bfloat162 ph; ph.x = h0; ph.y = h1;
                    __nv_bfloat162 pl; pl.x = l0; pl.y = l1;
                    *(__nv_bfloat162*)(Chi + co) = ph;
                    *(__nv_bfloat162*)(Clo + co) = pl;
                }
            }
        }
    }
}

// ---------------- logits + provisional argmax + ambiguity flag ----------------
__global__ void logits_kernel(const float* __restrict__ W2, const float* __restrict__ b2) {
    int warp = (blockIdx.x * blockDim.x + threadIdx.x) >> 5;
    int lane = threadIdx.x & 31;
    if (warp >= T_TOK) return;
    const float* hrow = g_hmid + (size_t)warp * 512;
    float s0 = 0.f, s1 = 0.f, s2 = 0.f;
    for (int k = lane * 4; k < 512; k += 128) {
        float4 h = *(const float4*)(hrow + k);
        const float* w = W2 + k * 3;
        s0 += h.x * w[0] + h.y * w[3] + h.z * w[6] + h.w * w[9];
        s1 += h.x * w[1] + h.y * w[4] + h.z * w[7] + h.w * w[10];
        s2 += h.x * w[2] + h.y * w[5] + h.z * w[8] + h.w * w[11];
    }
#pragma unroll
    for (int o = 16; o > 0; o >>= 1) {
        s0 += __shfl_xor_sync(0xffffffffu, s0, o);
        s1 += __shfl_xor_sync(0xffffffffu, s1, o);
        s2 += __shfl_xor_sync(0xffffffffu, s2, o);
    }
    if (lane == 0) {
        s0 += b2[0]; s1 += b2[1]; s2 += b2[2];
        int sel = 0; float best = s0;
        if (s1 > best) { best = s1; sel = 1; }
        if (s2 > best) { best = s2; sel = 2; }
        float second = (sel == 0) ? fmaxf(s1, s2) : (sel == 1 ? fmaxf(s0, s2) : fmaxf(s0, s1));
        g_sel[warp] = sel;
        if (best - second < 1e-3f) {
            int p = atomicAdd(&g_cnt[2], 1);
            g_fix[p] = warp;
        }
    }
}

// ---------------- fp32 exact recompute for ambiguous tokens ----------------
__global__ void fixup_kernel(const float* __restrict__ W1, const float* __restrict__ b1,
                             const float* __restrict__ W2, const float* __restrict__ b2) {
    __shared__ float hm[512];
    __shared__ float red[256];
    __shared__ float logit[3];
    int nfix = g_cnt[2];
    for (int i = blockIdx.x; i < nfix; i += gridDim.x) {
        int t = g_fix[i];
        const float* cr = g_combined + (size_t)t * HDIM;
        int j0 = threadIdx.x, j1 = threadIdx.x + 256;
        float a0 = b1[j0], a1 = b1[j1];
#pragma unroll 4
        for (int k = 0; k < HDIM; k++) {
            float c = __ldg(cr + k);
            a0 += c * W1[(size_t)k * 512 + j0];
            a1 += c * W1[(size_t)k * 512 + j1];
        }
        hm[j0] = fmaxf(a0, 0.f);
        hm[j1] = fmaxf(a1, 0.f);
        __syncthreads();
        for (int l = 0; l < 3; l++) {
            float p = hm[threadIdx.x] * W2[threadIdx.x * 3 + l] +
                      hm[threadIdx.x + 256] * W2[(threadIdx.x + 256) * 3 + l];
            red[threadIdx.x] = p; __syncthreads();
            for (int o = 128; o > 0; o >>= 1) {
                if (threadIdx.x < o) red[threadIdx.x] += red[threadIdx.x + o];
                __syncthreads();
            }
            if (threadIdx.x == 0) logit[l] = red[0] + b2[l];
            __syncthreads();
        }
        if (threadIdx.x == 0) {
            float s0 = logit[0], s1 = logit[1], s2 = logit[2];
            int sel = 0; float best = s0;
            if (s1 > best) { best = s1; sel = 1; }
            if (s2 > best) { sel = 2; }
            g_sel[t] = sel;
        }
        __syncthreads();
    }
}

__global__ void compact_kernel() {
    int t = blockIdx.x * blockDim.x + threadIdx.x;
    if (t >= T_TOK) return;
    int s = g_sel[t];
    if (s == 1)      { int p = atomicAdd(&g_cnt[0], 1); g_idx1[p] = t; }
    else if (s == 2) { int p = atomicAdd(&g_cnt[1], 1); g_idx2[p] = t; }
}

__global__ void copy0_kernel(const float* __restrict__ x, float* __restrict__ out) {
    int t = blockIdx.x;
    if (g_sel[t] != 0) return;
    const float4* src = (const float4*)(x + (size_t)t * HDIM);
    float4* dst = (float4*)(out + (size_t)t * HDIM);
    for (int i = threadIdx.x; i < HDIM / 4; i += blockDim.x) dst[i] = src[i];
}

// ---------------- launch ----------------
extern "C" void kernel_launch(void* const* d_in, const int* in_sizes, int n_in,
                              void* d_out, int out_size) {
    const float* x      = (const float*)d_in[0];
    const float* freq   = (const float*)d_in[1];
    const float* imp    = (const float*)d_in[2];
    const float* sel_W1 = (const float*)d_in[3];
    const float* sel_b1 = (const float*)d_in[4];
    const float* sel_W2 = (const float*)d_in[5];
    const float* sel_b2 = (const float*)d_in[6];
    const float* c1_W   = (const float*)d_in[7];
    const float* c1_b   = (const float*)d_in[8];
    const float* f1_W   = (const float*)d_in[9];
    const float* f1_b   = (const float*)d_in[10];
    const float* d1_W   = (const float*)d_in[11];
    const float* d1_b   = (const float*)d_in[12];
    const float* c2_W   = (const float*)d_in[13];
    const float* c2_b   = (const float*)d_in[14];
    const float* f2_W   = (const float*)d_in[15];
    const float* f2_b   = (const float*)d_in[16];
    const float* d2_W   = (const float*)d_in[17];
    const float* d2_b   = (const float*)d_in[18];
    float* out = (float*)d_out;

    bf16 *xhi, *xlo, *chi, *clo, *mAhi, *mAlo, *mBhi, *mBlo, *whi, *wlo;
    float *hmid;
    int *idx1, *idx2, *cnt;
    cudaGetSymbolAddress((void**)&xhi, g_xhi);
    cudaGetSymbolAddress((void**)&xlo, g_xlo);
    cudaGetSymbolAddress((void**)&chi, g_chi);
    cudaGetSymbolAddress((void**)&clo, g_clo);
    cudaGetSymbolAddress((void**)&mAhi, g_mAhi);
    cudaGetSymbolAddress((void**)&mAlo, g_mAlo);
    cudaGetSymbolAddress((void**)&mBhi, g_mBhi);
    cudaGetSymbolAddress((void**)&mBlo, g_mBlo);
    cudaGetSymbolAddress((void**)&whi, g_whi);
    cudaGetSymbolAddress((void**)&wlo, g_wlo);
    cudaGetSymbolAddress((void**)&hmid, g_hmid);
    cudaGetSymbolAddress((void**)&idx1, g_idx1);
    cudaGetSymbolAddress((void**)&idx2, g_idx2);
    cudaGetSymbolAddress((void**)&cnt, g_cnt);

    cudaFuncSetAttribute(gemm_mma, cudaFuncAttributeMaxDynamicSharedMemorySize, GEMM_SMEM);

    // 1) splits
    prep_kernel<<<(T_TOK * HDIM / 4 + 255) / 256, 256>>>(x, freq, imp);

    // 2) weight transpose + split  (grid: N/32 x K/32)  — NOTE: device pointers, not symbol shadows
    dim3 tb(32, 8);
    transpose_split_kernel<<<dim3(512 / 32, 2048 / 32), tb>>>(sel_W1, 2048, 512, whi + O_SELW1, wlo + O_SELW1);
    transpose_split_kernel<<<dim3(1024 / 32, 2048 / 32), tb>>>(c1_W, 2048, 1024, whi + O_C1, wlo + O_C1);
    transpose_split_kernel<<<dim3(1024 / 32, 1024 / 32), tb>>>(f1_W, 1024, 1024, whi + O_F1, wlo + O_F1);
    transpose_split_kernel<<<dim3(2048 / 32, 1024 / 32), tb>>>(d1_W, 1024, 2048, whi + O_D1, wlo + O_D1);
    transpose_split_kernel<<<dim3(512 / 32, 2048 / 32), tb>>>(c2_W, 2048, 512, whi + O_C2, wlo + O_C2);
    transpose_split_kernel<<<dim3(512 / 32, 512 / 32), tb>>>(f2_W, 512, 512, whi + O_F2, wlo + O_F2);
    transpose_split_kernel<<<dim3(2048 / 32, 512 / 32), tb>>>(d2_W, 512, 2048, whi + O_D2, wlo + O_D2);

    init_counters_kernel<<<1, 1>>>();

    // 3) selector hidden (fp32 out, relu)
    gemm_mma<<<dim3(512 / 128, 128), 256, GEMM_SMEM>>>(
        chi, clo, 2048, whi + O_SELW1, wlo + O_SELW1, 2048, sel_b1, 2048,
        hmid, 512, nullptr, nullptr, 0, nullptr, nullptr, nullptr, T_TOK, 1);

    // 4) logits + argmax (+ ambiguity fixup) + compaction
    logits_kernel<<<T_TOK / 8, 256>>>(sel_W2, sel_b2);
    fixup_kernel<<<64, 256>>>(sel_W1, sel_b1, sel_W2, sel_b2);
    compact_kernel<<<T_TOK / 256, 256>>>();
    copy0_kernel<<<T_TOK, 128>>>(x, out);

    // 5) expert 1
    gemm_mma<<<dim3(1024 / 128, 128), 256, GEMM_SMEM>>>(
        xhi, xlo, 2048, whi + O_C1, wlo + O_C1, 2048, c1_b, 2048,
        nullptr, 0, mAhi, mAlo, 1024, idx1, nullptr, cnt + 0, 0, 0);
    gemm_mma<<<dim3(1024 / 128, 128), 256, GEMM_SMEM>>>(
        mAhi, mAlo, 1024, whi + O_F1, wlo + O_F1, 1024, f1_b, 1024,
        nullptr, 0, mBhi, mBlo, 1024, nullptr, nullptr, cnt + 0, 0, 0);
    gemm_mma<<<dim3(2048 / 128, 128), 256, GEMM_SMEM>>>(
        mBhi, mBlo, 1024, whi + O_D1, wlo + O_D1, 1024, d1_b, 1024,
        out, 2048, nullptr, nullptr, 0, nullptr, idx1, cnt + 0, 0, 0);

    // 6) expert 2
    gemm_mma<<<dim3(512 / 128, 128), 256, GEMM_SMEM>>>(
        xhi, xlo, 2048, whi + O_C2, wlo + O_C2, 2048, c2_b, 2048,
        nullptr, 0, mAhi, mAlo, 512, idx2, nullptr, cnt + 1, 0, 0);
    gemm_mma<<<dim3(512 / 128, 128), 256, GEMM_SMEM>>>(
        mAhi, mAlo, 512, whi + O_F2, wlo + O_F2, 512, f2_b, 512,
        nullptr, 0, mBhi, mBlo, 512, nullptr, nullptr, cnt + 1, 0, 0);
    gemm_mma<<<dim3(2048 / 128, 128), 256, GEMM_SMEM>>>(
        mBhi, mBlo, 512, whi + O_D2, wlo + O_D2, 512, d2_b, 512,
        out, 2048, nullptr, nullptr, 0, nullptr, idx2, cnt + 1, 0, 0);
}